// round 16
// baseline (speedup 1.0000x reference)
#include <cuda_runtime.h>
#include <cuda_fp16.h>
#include <math.h>
#include <stdint.h>

#define BB 8
#define NN 1024
#define DIM 192
#define HEADS 16
#define DHEAD 64
#define INNER 1024
#define TOK (BB*NN)       // 8192
#define QKVN (3*INNER)    // 3072

// Scratch (allocation-free rule: __device__ globals)
__device__ __half g_hh[TOK*DIM];               // fp16 LN output
__device__ __half g_qkvh[(size_t)TOK*QKVN];    // fp16 qkv
__device__ __half g_attnh[(size_t)TOK*INNER];  // fp16 attention output
__device__ __half g_wqkvh[DIM*QKVN];           // fp16 weights (QSCALE folded)
__device__ __half g_wouth[INNER*DIM];

#define QSCALE 0.18033688f   // 0.125 * log2(e), folded into Q weight columns
#define ONES_H2 0x3C003C00u  // half2(1.0, 1.0)

__device__ __forceinline__ float ex2(float x){
    float y; asm("ex2.approx.f32 %0, %1;" : "=f"(y) : "f"(x)); return y;
}
__device__ __forceinline__ uint32_t ex2h2(uint32_t x){
    uint32_t y; asm("ex2.approx.f16x2 %0, %1;" : "=r"(y) : "r"(x)); return y;
}
// pack two fp32 -> half2 (lo = first arg)
__device__ __forceinline__ uint32_t f2h2(float lo, float hi){
    uint32_t r; asm("cvt.rn.f16x2.f32 %0, %1, %2;" : "=r"(r) : "f"(hi), "f"(lo)); return r;
}

// fp16 m16n8k16 with fp32 accum
__device__ __forceinline__ void mma_f16(float* c, const uint32_t* a, uint32_t b0, uint32_t b1){
    asm volatile("mma.sync.aligned.m16n8k16.row.col.f32.f16.f16.f32 "
        "{%0,%1,%2,%3}, {%4,%5,%6,%7}, {%8,%9}, {%0,%1,%2,%3};"
        : "+f"(c[0]), "+f"(c[1]), "+f"(c[2]), "+f"(c[3])
        : "r"(a[0]), "r"(a[1]), "r"(a[2]), "r"(a[3]), "r"(b0), "r"(b1));
}

__device__ __forceinline__ void ldsm4(uint32_t* r, uint32_t saddr){
    asm volatile("ldmatrix.sync.aligned.m8n8.x4.shared.b16 {%0,%1,%2,%3}, [%4];"
        : "=r"(r[0]), "=r"(r[1]), "=r"(r[2]), "=r"(r[3]) : "r"(saddr));
}
__device__ __forceinline__ void ldsm4t(uint32_t* r, uint32_t saddr){
    asm volatile("ldmatrix.sync.aligned.m8n8.x4.trans.shared.b16 {%0,%1,%2,%3}, [%4];"
        : "=r"(r[0]), "=r"(r[1]), "=r"(r[2]), "=r"(r[3]) : "r"(saddr));
}

__device__ __forceinline__ void cpa16(uint32_t dst, const void* src){
    asm volatile("cp.async.cg.shared.global [%0], [%1], 16;" :: "r"(dst), "l"(src));
}
__device__ __forceinline__ void cp_commit(){ asm volatile("cp.async.commit_group;"); }
template<int N> __device__ __forceinline__ void cp_wait(){
    asm volatile("cp.async.wait_group %0;" :: "n"(N));
}

// ---------------------------------------------------------------------------
// Weight conversion fp32 -> fp16 (QKV variant folds QSCALE into Q columns)
// ---------------------------------------------------------------------------
__global__ __launch_bounds__(256)
void cvt_wqkv_h(const float* __restrict__ src, __half* __restrict__ dst, int n){
    for (int i = blockIdx.x*256 + threadIdx.x; i < n; i += gridDim.x*256){
        int col = i % QKVN;
        float v = src[i];
        if (col < INNER) v *= QSCALE;
        dst[i] = __float2half_rn(v);
    }
}
__global__ __launch_bounds__(256)
void cvt_w_h(const float* __restrict__ src, __half* __restrict__ dst, int n){
    for (int i = blockIdx.x*256 + threadIdx.x; i < n; i += gridDim.x*256)
        dst[i] = __float2half_rn(src[i]);
}

// ---------------------------------------------------------------------------
// LayerNorm + adaLN modulation: one warp per token; fp16 output
// ---------------------------------------------------------------------------
__global__ __launch_bounds__(256)
void ln_mod_kernel(const float* __restrict__ x,
                   const float* __restrict__ shift,
                   const float* __restrict__ scale,
                   const float* __restrict__ w,
                   const float* __restrict__ bpar) {
    int warp = threadIdx.x >> 5;
    int lane = threadIdx.x & 31;
    int t = blockIdx.x * 8 + warp;
    const float* xr = x + (size_t)t * DIM;
    float v[6];
    float s = 0.f;
#pragma unroll
    for (int q = 0; q < 6; q++) { v[q] = xr[lane + q*32]; s += v[q]; }
#pragma unroll
    for (int o = 16; o; o >>= 1) s += __shfl_xor_sync(0xffffffffu, s, o);
    float mu = s * (1.f/DIM);
    float vs = 0.f;
#pragma unroll
    for (int q = 0; q < 6; q++) { float d = v[q]-mu; vs += d*d; }
#pragma unroll
    for (int o = 16; o; o >>= 1) vs += __shfl_xor_sync(0xffffffffu, vs, o);
    float rstd = rsqrtf(vs*(1.f/DIM) + 1e-5f);
    int bi = t >> 10;
#pragma unroll
    for (int q = 0; q < 6; q++) {
        int d = lane + q*32;
        float hn = (v[q]-mu)*rstd*w[d] + bpar[d];
        hn = hn * (1.f + scale[bi*DIM + d]) + shift[bi*DIM + d];
        g_hh[(size_t)t*DIM + d] = __float2half_rn(hn);
    }
}

// ---------------------------------------------------------------------------
// fp16 TC GEMM (m16n8k16, fp32 accum). BK=32, 256 thr, 8 warps.
// A [M][K] fp16, B [K][N] fp16 (B-frags via ldmatrix.trans).
// Ch != nullptr -> fp16 output (QKV); else fp32 + bias (out-proj).
// ---------------------------------------------------------------------------
#define AH_ROWB 80               // bytes per A smem row (32 halves + pad)

template<int BM, int BN, int WC>
__global__ __launch_bounds__(256, 2)
void gemm_f16(const __half* __restrict__ A, const __half* __restrict__ Bm,
              const float* __restrict__ bias, float* __restrict__ C,
              __half* __restrict__ Ch, int M, int Nn, int K){
    constexpr int NFR    = (BN/WC)/8;
    constexpr int AIT    = BM/64;
    constexpr int BIT    = BN/64;
    constexpr int BQ     = BN/8;
    constexpr int B_STRB = (BN+8)*2;
    constexpr int ABUF   = BM*AH_ROWB;
    constexpr int BBUF   = 32*B_STRB;
    extern __shared__ uint32_t smg[];
    uint32_t a_sh = (uint32_t)__cvta_generic_to_shared(smg);
    uint32_t b_sh = a_sh + 2*ABUF;
    int m0 = blockIdx.y*BM, n0 = blockIdx.x*BN;
    int tid = threadIdx.x;
    int w = tid>>5, lane = tid&31;
    int g = lane>>2, t = lane&3;
    int l8 = lane&7, q8 = lane>>3;
    int wm = w / WC, wn = w % WC;
    uint32_t a_off = (uint32_t)((q8&1)*8 + l8)*AH_ROWB + (q8>>1)*16;
    uint32_t b_off = (uint32_t)((q8&1)*8 + l8)*B_STRB + (q8>>1)*16;

    float acc[2][NFR][4] = {};

    auto issue = [&](int kt, int buf){
#pragma unroll
        for (int i = 0; i < AIT; i++){
            int fid = tid + i*256; int r = fid>>2, c = fid&3;
            cpa16(a_sh + (uint32_t)(buf*ABUF) + (uint32_t)r*AH_ROWB + c*16,
                  &A[(size_t)(m0+r)*K + kt + c*8]);
        }
#pragma unroll
        for (int i = 0; i < BIT; i++){
            int fid = tid + i*256; int r = fid/BQ, c = fid%BQ;
            cpa16(b_sh + (uint32_t)(buf*BBUF) + (uint32_t)r*B_STRB + c*16,
                  &Bm[(size_t)(kt+r)*Nn + n0 + c*8]);
        }
        cp_commit();
    };

    issue(0, 0);
    int nt = K/32;
    for (int it = 0; it < nt; it++){
        int buf = it & 1;
        cp_wait<0>();
        __syncthreads();
        if (it + 1 < nt) issue((it+1)*32, buf^1);
#pragma unroll
        for (int kc = 0; kc < 2; kc++){
            uint32_t af[2][4];
#pragma unroll
            for (int mf = 0; mf < 2; mf++)
                ldsm4(af[mf], a_sh + (uint32_t)(buf*ABUF)
                      + (uint32_t)(wm*32 + mf*16)*AH_ROWB + a_off + kc*32);
#pragma unroll
            for (int np = 0; np < NFR/2; np++){
                uint32_t bb[4];
                ldsm4t(bb, b_sh + (uint32_t)(buf*BBUF)
                       + (uint32_t)(kc*16)*B_STRB + b_off
                       + (uint32_t)(wn*(BN/WC) + np*16)*2);
                mma_f16(acc[0][2*np],   af[0], bb[0], bb[1]);
                mma_f16(acc[0][2*np+1], af[0], bb[2], bb[3]);
                mma_f16(acc[1][2*np],   af[1], bb[0], bb[1]);
                mma_f16(acc[1][2*np+1], af[1], bb[2], bb[3]);
            }
        }
        __syncthreads();
    }
#pragma unroll
    for (int mf = 0; mf < 2; mf++){
#pragma unroll
        for (int nf = 0; nf < NFR; nf++){
            int row = m0 + wm*32 + mf*16 + g;
            int col = n0 + wn*(BN/WC) + nf*8 + t*2;
            if (Ch){
                *(uint32_t*)&Ch[(size_t)row*Nn + col] =
                    f2h2(acc[mf][nf][0], acc[mf][nf][1]);
                *(uint32_t*)&Ch[(size_t)(row+8)*Nn + col] =
                    f2h2(acc[mf][nf][2], acc[mf][nf][3]);
            } else {
                float bx = bias ? bias[col] : 0.f;
                float by = bias ? bias[col+1] : 0.f;
                *(float2*)&C[(size_t)row*Nn + col] =
                    make_float2(acc[mf][nf][0]+bx, acc[mf][nf][1]+by);
                *(float2*)&C[(size_t)(row+8)*Nn + col] =
                    make_float2(acc[mf][nf][2]+bx, acc[mf][nf][3]+by);
            }
        }
    }
}

// ---------------------------------------------------------------------------
// Flash attention, fp16 m16n8k16 (fp32 accum). 128 thr / 64 q-rows per CTA
// (4 warps, warp owns 16 rows) -> 4 independent CTAs per SM so softmax and
// MMA phases of different CTAs interleave. Q frags in regs; P register-
// resident via f16x2 ex2; li via MMA vs all-ones B-frag; V via ldsm.trans.
// K/V cp.async double-buffered. Base-2 softmax (scale pre-folded).
// ---------------------------------------------------------------------------
#define ROWB   144                // bytes per K/V smem row (64 halves + pad)
#define KVBUF  (64*ROWB)          // 9216 B per buffer
#define ATTN_SMEM_BYTES (4*KVBUF) // 36864

__global__ __launch_bounds__(128, 4)
void attn_f16(const __half* __restrict__ qh, __half* __restrict__ outh){
    extern __shared__ uint32_t sm[];
    uint32_t ks_sh = (uint32_t)__cvta_generic_to_shared(sm);
    uint32_t vs_sh = ks_sh + 2*KVBUF;

    int qt = blockIdx.x, bh = blockIdx.y;  // 64-row q tiles (qt: 0..15)
    int b = bh>>4, h = bh&15;
    int tid = threadIdx.x, w = tid>>5, lane = tid&31;
    int g = lane>>2, t = lane&3;
    int l8 = lane&7, q8 = lane>>3;
    const __half* base = qh + (size_t)b*NN*QKVN + h*DHEAD;

    int arow = w*16 + (q8&1)*8 + l8;
    uint32_t a_off = (uint32_t)arow*ROWB + (q8>>1)*16;
    uint32_t sk_off = (uint32_t)((((q8>>1)&1)*8 + l8))*ROWB + (q8&1)*16;
    uint32_t vv_off = (uint32_t)(((q8&1)*8 + l8))*ROWB + (q8>>1)*16;

    // ---- Stage Q (64 rows, fp16) into K region, pull frags to registers ----
#pragma unroll
    for (int i = 0; i < 4; i++){
        int id = tid + i*128;
        int r = id>>3, c8 = id&7;
        cpa16(ks_sh + (uint32_t)r*ROWB + c8*16,
              &base[(size_t)(qt*64+r)*QKVN + c8*8]);
    }
    cp_commit(); cp_wait<0>();
    __syncthreads();
    uint32_t qf[4][4];
#pragma unroll
    for (int kc = 0; kc < 4; kc++)
        ldsm4(qf[kc], ks_sh + a_off + kc*32);
    __syncthreads();   // Ks free for K tiles

    auto issue = [&](int kt, int buf){
#pragma unroll
        for (int i = 0; i < 4; i++){
            int id = tid + i*128;
            int r = id>>3, c8 = id&7;
            const __half* kr = &base[(size_t)(kt*64+r)*QKVN + INNER + c8*8];
            cpa16(ks_sh + (uint32_t)(buf*KVBUF) + (uint32_t)r*ROWB + c8*16, kr);
            cpa16(vs_sh + (uint32_t)(buf*KVBUF) + (uint32_t)r*ROWB + c8*16, kr + INNER);
        }
        cp_commit();
    };

    float o[8][4] = {};
    float oS[4] = {};                     // ones-column accumulator (li sums)
    float mi0 = -INFINITY, mi1 = -INFINITY;

    issue(0, 0);
    for (int kt = 0; kt < 16; kt++){
        int buf = kt & 1;
        cp_wait<0>();
        __syncthreads();
        if (kt + 1 < 16) issue(kt+1, buf^1);

        // ---- S = Q @ K^T (log2 domain; scale pre-folded) ----
        float s[8][4] = {};
        uint32_t kbase = ks_sh + (uint32_t)(buf*KVBUF) + sk_off;
#pragma unroll
        for (int kc = 0; kc < 4; kc++){
#pragma unroll
            for (int np = 0; np < 4; np++){
                uint32_t kb[4];
                ldsm4(kb, kbase + (uint32_t)(np*16)*ROWB + kc*32);
                mma_f16(s[2*np],   qf[kc], kb[0], kb[1]);
                mma_f16(s[2*np+1], qf[kc], kb[2], kb[3]);
            }
        }

        // ---- Online softmax: max reduce + o rescale only ----
        float mx0 = -INFINITY, mx1 = -INFINITY;
#pragma unroll
        for (int nf = 0; nf < 8; nf++){
            mx0 = fmaxf(mx0, fmaxf(s[nf][0], s[nf][1]));
            mx1 = fmaxf(mx1, fmaxf(s[nf][2], s[nf][3]));
        }
        mx0 = fmaxf(mx0, __shfl_xor_sync(0xffffffffu, mx0, 1));
        mx0 = fmaxf(mx0, __shfl_xor_sync(0xffffffffu, mx0, 2));
        mx1 = fmaxf(mx1, __shfl_xor_sync(0xffffffffu, mx1, 1));
        mx1 = fmaxf(mx1, __shfl_xor_sync(0xffffffffu, mx1, 2));
        float mn0 = fmaxf(mi0, mx0), mn1 = fmaxf(mi1, mx1);
        float sc0 = ex2(mi0 - mn0), sc1 = ex2(mi1 - mn1);
        mi0 = mn0; mi1 = mn1;
#pragma unroll
        for (int nf = 0; nf < 8; nf++){
            o[nf][0] *= sc0; o[nf][1] *= sc0;
            o[nf][2] *= sc1; o[nf][3] *= sc1;
        }
        oS[0] *= sc0; oS[1] *= sc0; oS[2] *= sc1; oS[3] *= sc1;

        // ---- O += P @ V : exp fused into A-frag packing (f16x2 ex2);
        //      li accumulated by MMA vs constant all-ones B-frag ----
        uint32_t vbase = vs_sh + (uint32_t)(buf*KVBUF) + vv_off;
#pragma unroll
        for (int kc = 0; kc < 4; kc++){
            uint32_t pa[4];
            pa[0] = ex2h2(f2h2(s[2*kc][0]-mn0,   s[2*kc][1]-mn0));
            pa[1] = ex2h2(f2h2(s[2*kc][2]-mn1,   s[2*kc][3]-mn1));
            pa[2] = ex2h2(f2h2(s[2*kc+1][0]-mn0, s[2*kc+1][1]-mn0));
            pa[3] = ex2h2(f2h2(s[2*kc+1][2]-mn1, s[2*kc+1][3]-mn1));
            mma_f16(oS, pa, ONES_H2, ONES_H2);   // li partial sums
#pragma unroll
            for (int dp = 0; dp < 4; dp++){
                uint32_t vb[4];
                ldsm4t(vb, vbase + (uint32_t)(kc*16)*ROWB + dp*32);
                mma_f16(o[2*dp],   pa, vb[0], vb[1]);
                mma_f16(o[2*dp+1], pa, vb[2], vb[3]);
            }
        }
    }

    // Epilogue: li from ones-accumulator (all its cols equal the row sum)
    float inv0 = 1.f/oS[0], inv1 = 1.f/oS[2];
    int row = qt*64 + w*16 + g;
#pragma unroll
    for (int nf = 0; nf < 8; nf++){
        int col = h*DHEAD + nf*8 + t*2;
        *(uint32_t*)&outh[((size_t)(b*NN+row))*INNER + col]   =
            f2h2(o[nf][0]*inv0, o[nf][1]*inv0);
        *(uint32_t*)&outh[((size_t)(b*NN+row+8))*INNER + col] =
            f2h2(o[nf][2]*inv1, o[nf][3]*inv1);
    }
}

// ---------------------------------------------------------------------------
extern "C" void kernel_launch(void* const* d_in, const int* in_sizes, int n_in,
                              void* d_out, int out_size) {
    const float* x      = (const float*)d_in[0];
    const float* shift  = (const float*)d_in[1];
    const float* scale  = (const float*)d_in[2];
    const float* norm_w = (const float*)d_in[3];
    const float* norm_b = (const float*)d_in[4];
    const float* w_qkv  = (const float*)d_in[5];
    const float* w_out  = (const float*)d_in[6];
    const float* b_out  = (const float*)d_in[7];
    float* out = (float*)d_out;

    __half *hp, *qhp, *attnp, *wqp, *wop;
    cudaGetSymbolAddress((void**)&hp,    g_hh);
    cudaGetSymbolAddress((void**)&qhp,   g_qkvh);
    cudaGetSymbolAddress((void**)&attnp, g_attnh);
    cudaGetSymbolAddress((void**)&wqp,   g_wqkvh);
    cudaGetSymbolAddress((void**)&wop,   g_wouth);

    const int gsm_qkv = 2*128*AH_ROWB + 2*32*(128+8)*2;   // 37888
    const int gsm_out = 2*64*AH_ROWB  + 2*32*(64+8)*2;    // 19456
    cudaFuncSetAttribute((gemm_f16<128,128,2>),
                         cudaFuncAttributeMaxDynamicSharedMemorySize, gsm_qkv);
    cudaFuncSetAttribute((gemm_f16<64,64,4>),
                         cudaFuncAttributeMaxDynamicSharedMemorySize, gsm_out);
    cudaFuncSetAttribute(attn_f16,
                         cudaFuncAttributeMaxDynamicSharedMemorySize, ATTN_SMEM_BYTES);

    // Launch order keeps attention in the ncu capture slot (4th launch).
    cvt_wqkv_h<<<256, 256>>>(w_qkv, wqp, DIM*QKVN);
    ln_mod_kernel<<<TOK/8, 256>>>(x, shift, scale, norm_w, norm_b);
    gemm_f16<128,128,2><<<dim3(QKVN/128, TOK/128), 256, gsm_qkv>>>(
        hp, wqp, nullptr, nullptr, qhp, TOK, QKVN, DIM);
    attn_f16<<<dim3(16, BB*HEADS), 128, ATTN_SMEM_BYTES>>>(qhp, attnp);
    cvt_w_h<<<128, 256>>>(w_out, wop, INNER*DIM);
    gemm_f16<64,64,4><<<dim3(DIM/64, TOK/64), 256, gsm_out>>>(
        attnp, wop, b_out, out, nullptr, TOK, DIM, INNER);
}

// round 17
// speedup vs baseline: 1.0047x; 1.0047x over previous
#include <cuda_runtime.h>
#include <cuda_fp16.h>
#include <math.h>
#include <stdint.h>

#define BB 8
#define NN 1024
#define DIM 192
#define HEADS 16
#define DHEAD 64
#define INNER 1024
#define TOK (BB*NN)       // 8192
#define QKVN (3*INNER)    // 3072

// Scratch (allocation-free rule: __device__ globals)
__device__ __half g_hh[TOK*DIM];               // fp16 LN output
__device__ __half g_qkvh[(size_t)TOK*QKVN];    // fp16 qkv
__device__ __half g_attnh[(size_t)TOK*INNER];  // fp16 attention output
__device__ __half g_wqkvh[DIM*QKVN];           // fp16 weights (QSCALE folded)
__device__ __half g_wouth[INNER*DIM];

#define QSCALE 0.18033688f   // 0.125 * log2(e), folded into Q weight columns
#define ONES_H2 0x3C003C00u  // half2(1.0, 1.0)

__device__ __forceinline__ float ex2(float x){
    float y; asm("ex2.approx.f32 %0, %1;" : "=f"(y) : "f"(x)); return y;
}
__device__ __forceinline__ uint32_t ex2h2(uint32_t x){
    uint32_t y; asm("ex2.approx.f16x2 %0, %1;" : "=r"(y) : "r"(x)); return y;
}
// pack two fp32 -> half2 (lo = first arg)
__device__ __forceinline__ uint32_t f2h2(float lo, float hi){
    uint32_t r; asm("cvt.rn.f16x2.f32 %0, %1, %2;" : "=r"(r) : "f"(hi), "f"(lo)); return r;
}

// fp16 m16n8k16 with fp32 accum
__device__ __forceinline__ void mma_f16(float* c, const uint32_t* a, uint32_t b0, uint32_t b1){
    asm volatile("mma.sync.aligned.m16n8k16.row.col.f32.f16.f16.f32 "
        "{%0,%1,%2,%3}, {%4,%5,%6,%7}, {%8,%9}, {%0,%1,%2,%3};"
        : "+f"(c[0]), "+f"(c[1]), "+f"(c[2]), "+f"(c[3])
        : "r"(a[0]), "r"(a[1]), "r"(a[2]), "r"(a[3]), "r"(b0), "r"(b1));
}

__device__ __forceinline__ void ldsm4(uint32_t* r, uint32_t saddr){
    asm volatile("ldmatrix.sync.aligned.m8n8.x4.shared.b16 {%0,%1,%2,%3}, [%4];"
        : "=r"(r[0]), "=r"(r[1]), "=r"(r[2]), "=r"(r[3]) : "r"(saddr));
}
__device__ __forceinline__ void ldsm4t(uint32_t* r, uint32_t saddr){
    asm volatile("ldmatrix.sync.aligned.m8n8.x4.trans.shared.b16 {%0,%1,%2,%3}, [%4];"
        : "=r"(r[0]), "=r"(r[1]), "=r"(r[2]), "=r"(r[3]) : "r"(saddr));
}

__device__ __forceinline__ void cpa16(uint32_t dst, const void* src){
    asm volatile("cp.async.cg.shared.global [%0], [%1], 16;" :: "r"(dst), "l"(src));
}
__device__ __forceinline__ void cp_commit(){ asm volatile("cp.async.commit_group;"); }
template<int N> __device__ __forceinline__ void cp_wait(){
    asm volatile("cp.async.wait_group %0;" :: "n"(N));
}

// ---------------------------------------------------------------------------
// Weight conversion fp32 -> fp16 (QKV variant folds QSCALE into Q columns)
// ---------------------------------------------------------------------------
__global__ __launch_bounds__(256)
void cvt_wqkv_h(const float* __restrict__ src, __half* __restrict__ dst, int n){
    for (int i = blockIdx.x*256 + threadIdx.x; i < n; i += gridDim.x*256){
        int col = i % QKVN;
        float v = src[i];
        if (col < INNER) v *= QSCALE;
        dst[i] = __float2half_rn(v);
    }
}
__global__ __launch_bounds__(256)
void cvt_w_h(const float* __restrict__ src, __half* __restrict__ dst, int n){
    for (int i = blockIdx.x*256 + threadIdx.x; i < n; i += gridDim.x*256)
        dst[i] = __float2half_rn(src[i]);
}

// ---------------------------------------------------------------------------
// LayerNorm + adaLN modulation: one warp per token; fp16 output
// ---------------------------------------------------------------------------
__global__ __launch_bounds__(256)
void ln_mod_kernel(const float* __restrict__ x,
                   const float* __restrict__ shift,
                   const float* __restrict__ scale,
                   const float* __restrict__ w,
                   const float* __restrict__ bpar) {
    int warp = threadIdx.x >> 5;
    int lane = threadIdx.x & 31;
    int t = blockIdx.x * 8 + warp;
    const float* xr = x + (size_t)t * DIM;
    float v[6];
    float s = 0.f;
#pragma unroll
    for (int q = 0; q < 6; q++) { v[q] = xr[lane + q*32]; s += v[q]; }
#pragma unroll
    for (int o = 16; o; o >>= 1) s += __shfl_xor_sync(0xffffffffu, s, o);
    float mu = s * (1.f/DIM);
    float vs = 0.f;
#pragma unroll
    for (int q = 0; q < 6; q++) { float d = v[q]-mu; vs += d*d; }
#pragma unroll
    for (int o = 16; o; o >>= 1) vs += __shfl_xor_sync(0xffffffffu, vs, o);
    float rstd = rsqrtf(vs*(1.f/DIM) + 1e-5f);
    int bi = t >> 10;
#pragma unroll
    for (int q = 0; q < 6; q++) {
        int d = lane + q*32;
        float hn = (v[q]-mu)*rstd*w[d] + bpar[d];
        hn = hn * (1.f + scale[bi*DIM + d]) + shift[bi*DIM + d];
        g_hh[(size_t)t*DIM + d] = __float2half_rn(hn);
    }
}

// ---------------------------------------------------------------------------
// fp16 TC GEMM (m16n8k16, fp32 accum). BK=32, 256 thr, 8 warps.
// A [M][K] fp16, B [K][N] fp16 (B-frags via ldmatrix.trans).
// Ch != nullptr -> fp16 output (QKV); else fp32 + bias (out-proj).
// ---------------------------------------------------------------------------
#define AH_ROWB 80               // bytes per A smem row (32 halves + pad)

template<int BM, int BN, int WC>
__global__ __launch_bounds__(256, 2)
void gemm_f16(const __half* __restrict__ A, const __half* __restrict__ Bm,
              const float* __restrict__ bias, float* __restrict__ C,
              __half* __restrict__ Ch, int M, int Nn, int K){
    constexpr int NFR    = (BN/WC)/8;
    constexpr int AIT    = BM/64;
    constexpr int BIT    = BN/64;
    constexpr int BQ     = BN/8;
    constexpr int B_STRB = (BN+8)*2;
    constexpr int ABUF   = BM*AH_ROWB;
    constexpr int BBUF   = 32*B_STRB;
    extern __shared__ uint32_t smg[];
    uint32_t a_sh = (uint32_t)__cvta_generic_to_shared(smg);
    uint32_t b_sh = a_sh + 2*ABUF;
    int m0 = blockIdx.y*BM, n0 = blockIdx.x*BN;
    int tid = threadIdx.x;
    int w = tid>>5, lane = tid&31;
    int g = lane>>2, t = lane&3;
    int l8 = lane&7, q8 = lane>>3;
    int wm = w / WC, wn = w % WC;
    uint32_t a_off = (uint32_t)((q8&1)*8 + l8)*AH_ROWB + (q8>>1)*16;
    uint32_t b_off = (uint32_t)((q8&1)*8 + l8)*B_STRB + (q8>>1)*16;

    float acc[2][NFR][4] = {};

    auto issue = [&](int kt, int buf){
#pragma unroll
        for (int i = 0; i < AIT; i++){
            int fid = tid + i*256; int r = fid>>2, c = fid&3;
            cpa16(a_sh + (uint32_t)(buf*ABUF) + (uint32_t)r*AH_ROWB + c*16,
                  &A[(size_t)(m0+r)*K + kt + c*8]);
        }
#pragma unroll
        for (int i = 0; i < BIT; i++){
            int fid = tid + i*256; int r = fid/BQ, c = fid%BQ;
            cpa16(b_sh + (uint32_t)(buf*BBUF) + (uint32_t)r*B_STRB + c*16,
                  &Bm[(size_t)(kt+r)*Nn + n0 + c*8]);
        }
        cp_commit();
    };

    issue(0, 0);
    int nt = K/32;
    for (int it = 0; it < nt; it++){
        int buf = it & 1;
        cp_wait<0>();
        __syncthreads();
        if (it + 1 < nt) issue((it+1)*32, buf^1);
#pragma unroll
        for (int kc = 0; kc < 2; kc++){
            uint32_t af[2][4];
#pragma unroll
            for (int mf = 0; mf < 2; mf++)
                ldsm4(af[mf], a_sh + (uint32_t)(buf*ABUF)
                      + (uint32_t)(wm*32 + mf*16)*AH_ROWB + a_off + kc*32);
#pragma unroll
            for (int np = 0; np < NFR/2; np++){
                uint32_t bb[4];
                ldsm4t(bb, b_sh + (uint32_t)(buf*BBUF)
                       + (uint32_t)(kc*16)*B_STRB + b_off
                       + (uint32_t)(wn*(BN/WC) + np*16)*2);
                mma_f16(acc[0][2*np],   af[0], bb[0], bb[1]);
                mma_f16(acc[0][2*np+1], af[0], bb[2], bb[3]);
                mma_f16(acc[1][2*np],   af[1], bb[0], bb[1]);
                mma_f16(acc[1][2*np+1], af[1], bb[2], bb[3]);
            }
        }
        __syncthreads();
    }
#pragma unroll
    for (int mf = 0; mf < 2; mf++){
#pragma unroll
        for (int nf = 0; nf < NFR; nf++){
            int row = m0 + wm*32 + mf*16 + g;
            int col = n0 + wn*(BN/WC) + nf*8 + t*2;
            if (Ch){
                *(uint32_t*)&Ch[(size_t)row*Nn + col] =
                    f2h2(acc[mf][nf][0], acc[mf][nf][1]);
                *(uint32_t*)&Ch[(size_t)(row+8)*Nn + col] =
                    f2h2(acc[mf][nf][2], acc[mf][nf][3]);
            } else {
                float bx = bias ? bias[col] : 0.f;
                float by = bias ? bias[col+1] : 0.f;
                *(float2*)&C[(size_t)row*Nn + col] =
                    make_float2(acc[mf][nf][0]+bx, acc[mf][nf][1]+by);
                *(float2*)&C[(size_t)(row+8)*Nn + col] =
                    make_float2(acc[mf][nf][2]+bx, acc[mf][nf][3]+by);
            }
        }
    }
}

// ---------------------------------------------------------------------------
// Flash attention, fp16 m16n8k16 (fp32 accum). 256 thr, 128 q-rows/CTA
// (R15 shape). PV software-pipelined one tile behind S: PV(kt-1) MMAs sit
// between S(kt) and its max-reduce so the scheduler fills softmax stalls
// with tensor work. 4-deep K/V cp.async ring (issue kt+2 at iter top).
// Q frags in regs; P register-resident via f16x2 ex2; li via ones-MMA.
// ---------------------------------------------------------------------------
#define ROWB   144                // bytes per K/V smem row (64 halves + pad)
#define KVBUF  (64*ROWB)          // 9216 B per buffer
#define ATTN_SMEM_BYTES (8*KVBUF) // 4 K + 4 V buffers = 73728

__global__ __launch_bounds__(256, 2)
void attn_f16(const __half* __restrict__ qh, __half* __restrict__ outh){
    extern __shared__ uint32_t sm[];
    uint32_t ks_sh = (uint32_t)__cvta_generic_to_shared(sm);
    uint32_t vs_sh = ks_sh + 4*KVBUF;

    int qt = blockIdx.x, bh = blockIdx.y;  // 128-row q tiles
    int b = bh>>4, h = bh&15;
    int tid = threadIdx.x, w = tid>>5, lane = tid&31;
    int g = lane>>2, t = lane&3;
    int l8 = lane&7, q8 = lane>>3;
    const __half* base = qh + (size_t)b*NN*QKVN + h*DHEAD;

    int arow = w*16 + (q8&1)*8 + l8;
    uint32_t a_off = (uint32_t)arow*ROWB + (q8>>1)*16;
    uint32_t sk_off = (uint32_t)((((q8>>1)&1)*8 + l8))*ROWB + (q8&1)*16;
    uint32_t vv_off = (uint32_t)(((q8&1)*8 + l8))*ROWB + (q8>>1)*16;

    // ---- Stage Q (128 rows, fp16) into K buffers 0-1, frags to registers ----
#pragma unroll
    for (int i = 0; i < 4; i++){
        int id = tid + i*256;
        int r = id>>3, c8 = id&7;
        cpa16(ks_sh + (uint32_t)r*ROWB + c8*16,
              &base[(size_t)(qt*128+r)*QKVN + c8*8]);
    }
    cp_commit(); cp_wait<0>();
    __syncthreads();
    uint32_t qf[4][4];
#pragma unroll
    for (int kc = 0; kc < 4; kc++)
        ldsm4(qf[kc], ks_sh + a_off + kc*32);
    __syncthreads();   // staging region free for K tiles

    auto issue = [&](int kt, int buf){
#pragma unroll
        for (int i = 0; i < 2; i++){
            int id = tid + i*256;
            int r = id>>3, c8 = id&7;
            const __half* kr = &base[(size_t)(kt*64+r)*QKVN + INNER + c8*8];
            cpa16(ks_sh + (uint32_t)(buf*KVBUF) + (uint32_t)r*ROWB + c8*16, kr);
            cpa16(vs_sh + (uint32_t)(buf*KVBUF) + (uint32_t)r*ROWB + c8*16, kr + INNER);
        }
        cp_commit();
    };

    float o[8][4] = {};
    float oS[4] = {};                     // ones-column accumulator (li sums)
    float mi0 = -INFINITY, mi1 = -INFINITY;
    uint32_t pa_prev[4][4];               // P frags of tile kt-1

    issue(0, 0);
    issue(1, 1);
#pragma unroll 1
    for (int kt = 0; kt < 16; kt++){
        int buf = kt & 3;
        cp_wait<1>();       // tile kt resident (kt+1 may still be in flight)
        __syncthreads();    // all warps done reading buffer (kt+2)&3's old data
        if (kt + 2 < 16) issue(kt+2, (kt+2)&3);

        // ---- S = Q @ K^T (log2 domain; scale pre-folded) ----
        float s[8][4] = {};
        uint32_t kbase = ks_sh + (uint32_t)(buf*KVBUF) + sk_off;
#pragma unroll
        for (int kc = 0; kc < 4; kc++){
#pragma unroll
            for (int np = 0; np < 4; np++){
                uint32_t kb[4];
                ldsm4(kb, kbase + (uint32_t)(np*16)*ROWB + kc*32);
                mma_f16(s[2*np],   qf[kc], kb[0], kb[1]);
                mma_f16(s[2*np+1], qf[kc], kb[2], kb[3]);
            }
        }

        // ---- max reduce of S(kt) — interleaves with PV(kt-1) below ----
        float mx0 = -INFINITY, mx1 = -INFINITY;
#pragma unroll
        for (int nf = 0; nf < 8; nf++){
            mx0 = fmaxf(mx0, fmaxf(s[nf][0], s[nf][1]));
            mx1 = fmaxf(mx1, fmaxf(s[nf][2], s[nf][3]));
        }
        mx0 = fmaxf(mx0, __shfl_xor_sync(0xffffffffu, mx0, 1));
        mx0 = fmaxf(mx0, __shfl_xor_sync(0xffffffffu, mx0, 2));
        mx1 = fmaxf(mx1, __shfl_xor_sync(0xffffffffu, mx1, 1));
        mx1 = fmaxf(mx1, __shfl_xor_sync(0xffffffffu, mx1, 2));
        float mn0 = fmaxf(mi0, mx0), mn1 = fmaxf(mi1, mx1);
        float sc0 = ex2(mi0 - mn0), sc1 = ex2(mi1 - mn1);
        mi0 = mn0; mi1 = mn1;

        // ---- PV(kt-1): independent of the max chain above ----
        if (kt > 0){
            uint32_t vbase = vs_sh + (uint32_t)(((kt-1)&3)*KVBUF) + vv_off;
#pragma unroll
            for (int kc = 0; kc < 4; kc++){
#pragma unroll
                for (int dp = 0; dp < 4; dp++){
                    uint32_t vb[4];
                    ldsm4t(vb, vbase + (uint32_t)(kc*16)*ROWB + dp*32);
                    mma_f16(o[2*dp],   pa_prev[kc], vb[0], vb[1]);
                    mma_f16(o[2*dp+1], pa_prev[kc], vb[2], vb[3]);
                }
            }
        }

        // ---- rescale o,oS to mn(kt); pack P(kt); li partial sums ----
#pragma unroll
        for (int nf = 0; nf < 8; nf++){
            o[nf][0] *= sc0; o[nf][1] *= sc0;
            o[nf][2] *= sc1; o[nf][3] *= sc1;
        }
        oS[0] *= sc0; oS[1] *= sc0; oS[2] *= sc1; oS[3] *= sc1;
#pragma unroll
        for (int kc = 0; kc < 4; kc++){
            pa_prev[kc][0] = ex2h2(f2h2(s[2*kc][0]-mn0,   s[2*kc][1]-mn0));
            pa_prev[kc][1] = ex2h2(f2h2(s[2*kc][2]-mn1,   s[2*kc][3]-mn1));
            pa_prev[kc][2] = ex2h2(f2h2(s[2*kc+1][0]-mn0, s[2*kc+1][1]-mn0));
            pa_prev[kc][3] = ex2h2(f2h2(s[2*kc+1][2]-mn1, s[2*kc+1][3]-mn1));
            mma_f16(oS, pa_prev[kc], ONES_H2, ONES_H2);
        }
    }

    // ---- final PV(15) ----
    {
        uint32_t vbase = vs_sh + (uint32_t)((15&3)*KVBUF) + vv_off;
#pragma unroll
        for (int kc = 0; kc < 4; kc++){
#pragma unroll
            for (int dp = 0; dp < 4; dp++){
                uint32_t vb[4];
                ldsm4t(vb, vbase + (uint32_t)(kc*16)*ROWB + dp*32);
                mma_f16(o[2*dp],   pa_prev[kc], vb[0], vb[1]);
                mma_f16(o[2*dp+1], pa_prev[kc], vb[2], vb[3]);
            }
        }
    }

    // Epilogue: li from ones-accumulator (all its cols equal the row sum)
    float inv0 = 1.f/oS[0], inv1 = 1.f/oS[2];
    int row = qt*128 + w*16 + g;
#pragma unroll
    for (int nf = 0; nf < 8; nf++){
        int col = h*DHEAD + nf*8 + t*2;
        *(uint32_t*)&outh[((size_t)(b*NN+row))*INNER + col]   =
            f2h2(o[nf][0]*inv0, o[nf][1]*inv0);
        *(uint32_t*)&outh[((size_t)(b*NN+row+8))*INNER + col] =
            f2h2(o[nf][2]*inv1, o[nf][3]*inv1);
    }
}

// ---------------------------------------------------------------------------
extern "C" void kernel_launch(void* const* d_in, const int* in_sizes, int n_in,
                              void* d_out, int out_size) {
    const float* x      = (const float*)d_in[0];
    const float* shift  = (const float*)d_in[1];
    const float* scale  = (const float*)d_in[2];
    const float* norm_w = (const float*)d_in[3];
    const float* norm_b = (const float*)d_in[4];
    const float* w_qkv  = (const float*)d_in[5];
    const float* w_out  = (const float*)d_in[6];
    const float* b_out  = (const float*)d_in[7];
    float* out = (float*)d_out;

    __half *hp, *qhp, *attnp, *wqp, *wop;
    cudaGetSymbolAddress((void**)&hp,    g_hh);
    cudaGetSymbolAddress((void**)&qhp,   g_qkvh);
    cudaGetSymbolAddress((void**)&attnp, g_attnh);
    cudaGetSymbolAddress((void**)&wqp,   g_wqkvh);
    cudaGetSymbolAddress((void**)&wop,   g_wouth);

    const int gsm_qkv = 2*128*AH_ROWB + 2*32*(128+8)*2;   // 37888
    const int gsm_out = 2*64*AH_ROWB  + 2*32*(64+8)*2;    // 19456
    cudaFuncSetAttribute((gemm_f16<128,128,2>),
                         cudaFuncAttributeMaxDynamicSharedMemorySize, gsm_qkv);
    cudaFuncSetAttribute((gemm_f16<64,64,4>),
                         cudaFuncAttributeMaxDynamicSharedMemorySize, gsm_out);
    cudaFuncSetAttribute(attn_f16,
                         cudaFuncAttributeMaxDynamicSharedMemorySize, ATTN_SMEM_BYTES);

    // Launch order keeps attention in the ncu capture slot (4th launch).
    cvt_wqkv_h<<<256, 256>>>(w_qkv, wqp, DIM*QKVN);
    ln_mod_kernel<<<TOK/8, 256>>>(x, shift, scale, norm_w, norm_b);
    gemm_f16<128,128,2><<<dim3(QKVN/128, TOK/128), 256, gsm_qkv>>>(
        hp, wqp, nullptr, nullptr, qhp, TOK, QKVN, DIM);
    attn_f16<<<dim3(8, BB*HEADS), 256, ATTN_SMEM_BYTES>>>(qhp, attnp);
    cvt_w_h<<<128, 256>>>(w_out, wop, INNER*DIM);
    gemm_f16<64,64,4><<<dim3(DIM/64, TOK/64), 256, gsm_out>>>(
        attnp, wop, b_out, out, nullptr, TOK, DIM, INNER);
}